// round 5
// baseline (speedup 1.0000x reference)
#include <cuda_runtime.h>
#include <cuda_fp16.h>

#define N_NODES_MAX 50000
#define N_EDGES_MAX 800000
#define D_FEAT 64
#define D_OUT 64
#define N_REL 8
#define K_DIM 256
#define NODE_TILE 128
#define KC 32            /* 8 i * 4 b per chunk */
#define NCHUNK (K_DIM / KC)
#define TBLOCK 256

typedef unsigned long long ull;

// device scratch (static allocation per harness rules)
__device__ __half g_y[(size_t)N_NODES_MAX * D_OUT];     // 6.4 MB
__device__ int    g_cnt[N_NODES_MAX];                   // counts -> cursors
__device__ int    g_start[N_NODES_MAX + 1];             // CSR row starts
__device__ uint2  g_elist[N_EDGES_MAX];                 // (src, w-bits) by dst

#define FMA2(acc, a, b) \
    asm("fma.rn.f32x2 %0, %1, %2, %0;" : "+l"(acc) : "l"(a), "l"(b))

__device__ __forceinline__ ull pack2(float v) {
    ull r; unsigned u = __float_as_uint(v);
    asm("mov.b64 %0, {%1, %1};" : "=l"(r) : "r"(u));
    return r;
}
__device__ __forceinline__ ull pack2pair(float lo, float hi) {
    ull r;
    asm("mov.b64 %0, {%1, %2};" : "=l"(r)
        : "r"(__float_as_uint(lo)), "r"(__float_as_uint(hi)));
    return r;
}
__device__ __forceinline__ float2 unpack2(ull v) {
    unsigned lo, hi;
    asm("mov.b64 {%0, %1}, %2;" : "=r"(lo), "=r"(hi) : "l"(v));
    return make_float2(__uint_as_float(lo), __uint_as_float(hi));
}

// ---------------------------------------------------------------------------
// Transform: y[n,o] = sum_k z[n,k] wb[k,o],  z[n,(i,b)] = sum_r x[n,i,r] wrel[r,b]
// smem: wb_s fp32 [256][64] (64KB), z double-buffer [2][32][128] swizzled (32KB)
// Thread tile: 8 nodes x 4 outs, f32x2 over out-pairs. One barrier per chunk.
// ---------------------------------------------------------------------------
extern "C" __global__ void __launch_bounds__(TBLOCK, 2)
rgcn_transform(const float* __restrict__ x,
               const float* __restrict__ w_bases,
               const float* __restrict__ w_rel,
               int n_nodes, int n_tiles)
{
    extern __shared__ float smem[];
    float* wb_s    = smem;                           // 16384 floats
    float* z_s     = smem + K_DIM * D_OUT;           // 2*32*128 floats
    ull*   wrel2_s = (ull*)(z_s + 2 * KC * NODE_TILE);

    const int t = threadIdx.x;

    if (t < N_REL * 2) {
        int r = t >> 1, bp = t & 1;
        wrel2_s[r * 2 + bp] = pack2pair(w_rel[r * 4 + 2 * bp],
                                        w_rel[r * 4 + 2 * bp + 1]);
    }
    // wb_s[(i*4+b)*64 + o] = w_bases[b][i][o]
    for (int idx = t; idx < K_DIM * D_OUT; idx += TBLOCK) {
        int k = idx >> 6, o = idx & 63;
        int b = k & 3,   i = k >> 2;
        wb_s[idx] = w_bases[(b * D_FEAT + i) * D_OUT + o];
    }
    __syncthreads();

    const int og = t & 15;        // 16 out groups * 4 outs
    const int ng = t >> 4;        // 16 node groups * 8 nodes
    const int ii_a = t & 7;       // Phase A: i within chunk
    const int nb_a = t >> 3;      // Phase A: node base (0..31)

    for (int tile = blockIdx.x; tile < n_tiles; tile += gridDim.x) {
        const int node0 = tile * NODE_TILE;

        ull acc[8][2];
        #pragma unroll
        for (int j = 0; j < 8; j++) { acc[j][0] = 0ull; acc[j][1] = 0ull; }

        for (int c = 0; c < NCHUNK; c++) {
            float* zb_buf = z_s + (c & 1) * (KC * NODE_TILE);

            // ---- Phase A: z chunk (8 i, 4 b) ---------------------------
            #pragma unroll
            for (int it = 0; it < 4; it++) {
                int n = nb_a + it * 32;
                int node = node0 + n;
                ull zp0 = 0ull, zp1 = 0ull;
                if (node < n_nodes) {
                    const float4* xr = (const float4*)
                        (x + ((size_t)node * D_FEAT + (c * 8 + ii_a)) * N_REL);
                    float4 x0 = xr[0];
                    float4 x1 = xr[1];
                    ull xp;
                    xp = pack2(x0.x); FMA2(zp0, xp, wrel2_s[0]);  FMA2(zp1, xp, wrel2_s[1]);
                    xp = pack2(x0.y); FMA2(zp0, xp, wrel2_s[2]);  FMA2(zp1, xp, wrel2_s[3]);
                    xp = pack2(x0.z); FMA2(zp0, xp, wrel2_s[4]);  FMA2(zp1, xp, wrel2_s[5]);
                    xp = pack2(x0.w); FMA2(zp0, xp, wrel2_s[6]);  FMA2(zp1, xp, wrel2_s[7]);
                    xp = pack2(x1.x); FMA2(zp0, xp, wrel2_s[8]);  FMA2(zp1, xp, wrel2_s[9]);
                    xp = pack2(x1.y); FMA2(zp0, xp, wrel2_s[10]); FMA2(zp1, xp, wrel2_s[11]);
                    xp = pack2(x1.z); FMA2(zp0, xp, wrel2_s[12]); FMA2(zp1, xp, wrel2_s[13]);
                    xp = pack2(x1.w); FMA2(zp0, xp, wrel2_s[14]); FMA2(zp1, xp, wrel2_s[15]);
                }
                float2 zlo = unpack2(zp0);   // b0, b1
                float2 zhi = unpack2(zp1);   // b2, b3
                // swizzled: node-group (n>>2) stored at slot (n>>2)^ii
                int spos = ((((n >> 2) ^ ii_a) << 2) | (n & 3));
                float* zb = zb_buf + (ii_a * 4) * NODE_TILE + spos;
                zb[0 * NODE_TILE] = zlo.x;
                zb[1 * NODE_TILE] = zlo.y;
                zb[2 * NODE_TILE] = zhi.x;
                zb[3 * NODE_TILE] = zhi.y;
            }
            __syncthreads();   // sole barrier per chunk (double-buffered ring)

            // ---- Phase B: acc += z_chunk @ wb_chunk --------------------
            const float* wb_c = wb_s + (c * KC) * D_OUT + og * 4;
            #pragma unroll 8
            for (int kk = 0; kk < KC; kk++) {
                int ii = kk >> 2;
                const float* zrow = zb_buf + kk * NODE_TILE;
                float4 za = *(const float4*)(zrow + (((2 * ng) ^ ii) << 2));
                float4 zb = *(const float4*)(zrow + (((2 * ng + 1) ^ ii) << 2));
                ulonglong2 w2 = *(const ulonglong2*)(wb_c + kk * D_OUT);
                ull zp;
                zp = pack2(za.x); FMA2(acc[0][0], zp, w2.x); FMA2(acc[0][1], zp, w2.y);
                zp = pack2(za.y); FMA2(acc[1][0], zp, w2.x); FMA2(acc[1][1], zp, w2.y);
                zp = pack2(za.z); FMA2(acc[2][0], zp, w2.x); FMA2(acc[2][1], zp, w2.y);
                zp = pack2(za.w); FMA2(acc[3][0], zp, w2.x); FMA2(acc[3][1], zp, w2.y);
                zp = pack2(zb.x); FMA2(acc[4][0], zp, w2.x); FMA2(acc[4][1], zp, w2.y);
                zp = pack2(zb.y); FMA2(acc[5][0], zp, w2.x); FMA2(acc[5][1], zp, w2.y);
                zp = pack2(zb.z); FMA2(acc[6][0], zp, w2.x); FMA2(acc[6][1], zp, w2.y);
                zp = pack2(zb.w); FMA2(acc[7][0], zp, w2.x); FMA2(acc[7][1], zp, w2.y);
            }
        }

        // ---- store y (fp16) -------------------------------------------
        #pragma unroll
        for (int j = 0; j < 8; j++) {
            int node = node0 + ng * 8 + j;
            if (node < n_nodes) {
                float2 a = unpack2(acc[j][0]);
                float2 b = unpack2(acc[j][1]);
                __half2 h0 = __floats2half2_rn(a.x, a.y);
                __half2 h1 = __floats2half2_rn(b.x, b.y);
                uint2 v;
                v.x = *(unsigned*)&h0;
                v.y = *(unsigned*)&h1;
                *(uint2*)(g_y + (size_t)node * D_OUT + og * 4) = v;
            }
        }
        // no tile-end barrier: next chunk 0 writes the other z buffer
    }
}

// ---------------------------------------------------------------------------
// CSR build: zero -> histogram -> scan -> fill
// ---------------------------------------------------------------------------
extern "C" __global__ void rgcn_zero(int n_nodes)
{
    int i = blockIdx.x * blockDim.x + threadIdx.x;
    if (i < n_nodes) g_cnt[i] = 0;
}

extern "C" __global__ void rgcn_hist(const int* __restrict__ edst, int n_edges)
{
    int e = blockIdx.x * blockDim.x + threadIdx.x;
    if (e < n_edges) atomicAdd(&g_cnt[edst[e]], 1);
}

// single block, 1024 threads: chunked block-wide exclusive scan
extern "C" __global__ void __launch_bounds__(1024, 1)
rgcn_scan(int n_nodes)
{
    __shared__ int wtot[32];
    const int t = threadIdx.x, lane = t & 31, wid = t >> 5;
    int running = 0;
    const int nchunks = (n_nodes + 1023) >> 10;
    for (int c = 0; c < nchunks; c++) {
        int idx = (c << 10) + t;
        int v = (idx < n_nodes) ? g_cnt[idx] : 0;
        int s = v;
        #pragma unroll
        for (int d = 1; d < 32; d <<= 1) {
            int u = __shfl_up_sync(0xffffffffu, s, d);
            if (lane >= d) s += u;
        }
        if (lane == 31) wtot[wid] = s;
        __syncthreads();
        if (wid == 0) {
            int wv = wtot[lane];
            #pragma unroll
            for (int d = 1; d < 32; d <<= 1) {
                int u = __shfl_up_sync(0xffffffffu, wv, d);
                if (lane >= d) wv += u;
            }
            wtot[lane] = wv;
        }
        __syncthreads();
        int excl = s - v + (wid ? wtot[wid - 1] : 0);
        int total = wtot[31];
        if (idx < n_nodes) {
            int st = running + excl;
            g_start[idx] = st;
            g_cnt[idx] = st;      // cursor for fill
        }
        running += total;
        __syncthreads();
    }
    if (t == 0) g_start[n_nodes] = running;
}

extern "C" __global__ void rgcn_fill(const int*   __restrict__ esrc,
                                     const int*   __restrict__ edst,
                                     const float* __restrict__ ew,
                                     int n_edges)
{
    int e = blockIdx.x * blockDim.x + threadIdx.x;
    if (e >= n_edges) return;
    int d = edst[e];
    int pos = atomicAdd(&g_cnt[d], 1);
    g_elist[pos] = make_uint2((unsigned)esrc[e], __float_as_uint(ew[e]));
}

// ---------------------------------------------------------------------------
// Aggregate: one warp per dst node; each lane owns 2 outputs. No atomics.
// ---------------------------------------------------------------------------
__device__ __forceinline__ float2 yfrag(unsigned src, int lane)
{
    unsigned q = *((const unsigned*)g_y + ((size_t)src << 5) + lane);
    __half2 h; *(unsigned*)&h = q;
    return __half22float2(h);
}

extern "C" __global__ void __launch_bounds__(256, 8)
rgcn_aggregate(float* __restrict__ out, int n_nodes)
{
    int gid = blockIdx.x * blockDim.x + threadIdx.x;
    int n = gid >> 5;
    if (n >= n_nodes) return;
    int lane = gid & 31;
    int e  = g_start[n];
    int e1 = g_start[n + 1];
    float2 acc = make_float2(0.f, 0.f);

    for (; e + 4 <= e1; e += 4) {
        uint2 p0 = g_elist[e];
        uint2 p1 = g_elist[e + 1];
        uint2 p2 = g_elist[e + 2];
        uint2 p3 = g_elist[e + 3];
        float2 f0 = yfrag(p0.x, lane);
        float2 f1 = yfrag(p1.x, lane);
        float2 f2 = yfrag(p2.x, lane);
        float2 f3 = yfrag(p3.x, lane);
        float w0 = __uint_as_float(p0.y), w1 = __uint_as_float(p1.y);
        float w2 = __uint_as_float(p2.y), w3 = __uint_as_float(p3.y);
        acc.x += w0 * f0.x; acc.y += w0 * f0.y;
        acc.x += w1 * f1.x; acc.y += w1 * f1.y;
        acc.x += w2 * f2.x; acc.y += w2 * f2.y;
        acc.x += w3 * f3.x; acc.y += w3 * f3.y;
    }
    for (; e < e1; e++) {
        uint2 p = g_elist[e];
        float2 f = yfrag(p.x, lane);
        float w = __uint_as_float(p.y);
        acc.x += w * f.x; acc.y += w * f.y;
    }
    *(float2*)(out + (size_t)n * D_OUT + lane * 2) = acc;
}

// ---------------------------------------------------------------------------
extern "C" void kernel_launch(void* const* d_in, const int* in_sizes, int n_in,
                              void* d_out, int out_size)
{
    const float* x    = (const float*)d_in[0];
    const int*   esrc = (const int*)  d_in[1];
    const int*   edst = (const int*)  d_in[2];
    const float* ew   = (const float*)d_in[3];
    const float* wb   = (const float*)d_in[4];
    const float* wrel = (const float*)d_in[5];
    float* out = (float*)d_out;

    const int n_nodes = in_sizes[0] / (D_FEAT * N_REL);
    const int n_edges = in_sizes[1];
    const int n_tiles = (n_nodes + NODE_TILE - 1) / NODE_TILE;

    const int smem_bytes = K_DIM * D_OUT * sizeof(float)
                         + 2 * KC * NODE_TILE * sizeof(float)
                         + N_REL * 2 * sizeof(ull);
    cudaFuncSetAttribute(rgcn_transform,
                         cudaFuncAttributeMaxDynamicSharedMemorySize, smem_bytes);

    // node transform (independent of edges)
    rgcn_transform<<<296, TBLOCK, smem_bytes>>>(x, wb, wrel, n_nodes, n_tiles);

    // CSR build by dst
    rgcn_zero<<<(n_nodes + 255) / 256, 256>>>(n_nodes);
    rgcn_hist<<<(n_edges + 255) / 256, 256>>>(edst, n_edges);
    rgcn_scan<<<1, 1024>>>(n_nodes);
    rgcn_fill<<<(n_edges + 255) / 256, 256>>>(esrc, edst, ew, n_edges);

    // gather-aggregate (writes every output element; no memset needed)
    int total_thr = n_nodes * 32;
    rgcn_aggregate<<<(total_thr + 255) / 256, 256>>>(out, n_nodes);
}

// round 6
// speedup vs baseline: 1.1897x; 1.1897x over previous
#include <cuda_runtime.h>
#include <cuda_fp16.h>

#define N_NODES_MAX 50000
#define N_EDGES_MAX 800000
#define D_FEAT 64
#define D_OUT 64
#define N_REL 8
#define K_DIM 256
#define NODE_TILE 128
#define KC 32            /* 8 i * 4 b per chunk */
#define NCHUNK (K_DIM / KC)
#define TBLOCK 256
#define SCAN_PER 4096    /* elements per scan block (1024 thr x 4) */

typedef unsigned long long ull;

// device scratch (static allocation per harness rules)
__device__ __half g_y[(size_t)N_NODES_MAX * D_OUT];     // 6.4 MB
__device__ int    g_cnt[N_NODES_MAX];                   // counts -> cursors
__device__ int    g_start[N_NODES_MAX + 1];             // CSR row starts
__device__ uint2  g_elist[N_EDGES_MAX];                 // (src, w-bits) by dst
__device__ int    g_bsum[64];                           // scan block sums

#define FMA2(acc, a, b) \
    asm("fma.rn.f32x2 %0, %1, %2, %0;" : "+l"(acc) : "l"(a), "l"(b))

__device__ __forceinline__ ull pack2(float v) {
    ull r; unsigned u = __float_as_uint(v);
    asm("mov.b64 %0, {%1, %1};" : "=l"(r) : "r"(u));
    return r;
}
__device__ __forceinline__ ull pack2pair(float lo, float hi) {
    ull r;
    asm("mov.b64 %0, {%1, %2};" : "=l"(r)
        : "r"(__float_as_uint(lo)), "r"(__float_as_uint(hi)));
    return r;
}
__device__ __forceinline__ float2 unpack2(ull v) {
    unsigned lo, hi;
    asm("mov.b64 {%0, %1}, %2;" : "=r"(lo), "=r"(hi) : "l"(v));
    return make_float2(__uint_as_float(lo), __uint_as_float(hi));
}

// ---------------------------------------------------------------------------
// Transform: y[n,o] = sum_k z[n,k] wb[k,o],  z[n,(i,b)] = sum_r x[n,i,r] wrel[r,b]
// ---------------------------------------------------------------------------
extern "C" __global__ void __launch_bounds__(TBLOCK, 2)
rgcn_transform(const float* __restrict__ x,
               const float* __restrict__ w_bases,
               const float* __restrict__ w_rel,
               int n_nodes, int n_tiles)
{
    extern __shared__ float smem[];
    float* wb_s    = smem;                           // 16384 floats
    float* z_s     = smem + K_DIM * D_OUT;           // 2*32*128 floats
    ull*   wrel2_s = (ull*)(z_s + 2 * KC * NODE_TILE);

    const int t = threadIdx.x;

    if (t < N_REL * 2) {
        int r = t >> 1, bp = t & 1;
        wrel2_s[r * 2 + bp] = pack2pair(w_rel[r * 4 + 2 * bp],
                                        w_rel[r * 4 + 2 * bp + 1]);
    }
    for (int idx = t; idx < K_DIM * D_OUT; idx += TBLOCK) {
        int k = idx >> 6, o = idx & 63;
        int b = k & 3,   i = k >> 2;
        wb_s[idx] = w_bases[(b * D_FEAT + i) * D_OUT + o];
    }
    __syncthreads();

    const int og = t & 15;        // 16 out groups * 4 outs
    const int ng = t >> 4;        // 16 node groups * 8 nodes
    const int ii_a = t & 7;       // Phase A: i within chunk
    const int nb_a = t >> 3;      // Phase A: node base (0..31)

    for (int tile = blockIdx.x; tile < n_tiles; tile += gridDim.x) {
        const int node0 = tile * NODE_TILE;

        ull acc[8][2];
        #pragma unroll
        for (int j = 0; j < 8; j++) { acc[j][0] = 0ull; acc[j][1] = 0ull; }

        for (int c = 0; c < NCHUNK; c++) {
            float* zb_buf = z_s + (c & 1) * (KC * NODE_TILE);

            #pragma unroll
            for (int it = 0; it < 4; it++) {
                int n = nb_a + it * 32;
                int node = node0 + n;
                ull zp0 = 0ull, zp1 = 0ull;
                if (node < n_nodes) {
                    const float4* xr = (const float4*)
                        (x + ((size_t)node * D_FEAT + (c * 8 + ii_a)) * N_REL);
                    float4 x0 = xr[0];
                    float4 x1 = xr[1];
                    ull xp;
                    xp = pack2(x0.x); FMA2(zp0, xp, wrel2_s[0]);  FMA2(zp1, xp, wrel2_s[1]);
                    xp = pack2(x0.y); FMA2(zp0, xp, wrel2_s[2]);  FMA2(zp1, xp, wrel2_s[3]);
                    xp = pack2(x0.z); FMA2(zp0, xp, wrel2_s[4]);  FMA2(zp1, xp, wrel2_s[5]);
                    xp = pack2(x0.w); FMA2(zp0, xp, wrel2_s[6]);  FMA2(zp1, xp, wrel2_s[7]);
                    xp = pack2(x1.x); FMA2(zp0, xp, wrel2_s[8]);  FMA2(zp1, xp, wrel2_s[9]);
                    xp = pack2(x1.y); FMA2(zp0, xp, wrel2_s[10]); FMA2(zp1, xp, wrel2_s[11]);
                    xp = pack2(x1.z); FMA2(zp0, xp, wrel2_s[12]); FMA2(zp1, xp, wrel2_s[13]);
                    xp = pack2(x1.w); FMA2(zp0, xp, wrel2_s[14]); FMA2(zp1, xp, wrel2_s[15]);
                }
                float2 zlo = unpack2(zp0);
                float2 zhi = unpack2(zp1);
                int spos = ((((n >> 2) ^ ii_a) << 2) | (n & 3));
                float* zb = zb_buf + (ii_a * 4) * NODE_TILE + spos;
                zb[0 * NODE_TILE] = zlo.x;
                zb[1 * NODE_TILE] = zlo.y;
                zb[2 * NODE_TILE] = zhi.x;
                zb[3 * NODE_TILE] = zhi.y;
            }
            __syncthreads();

            const float* wb_c = wb_s + (c * KC) * D_OUT + og * 4;
            #pragma unroll 8
            for (int kk = 0; kk < KC; kk++) {
                int ii = kk >> 2;
                const float* zrow = zb_buf + kk * NODE_TILE;
                float4 za = *(const float4*)(zrow + (((2 * ng) ^ ii) << 2));
                float4 zb = *(const float4*)(zrow + (((2 * ng + 1) ^ ii) << 2));
                ulonglong2 w2 = *(const ulonglong2*)(wb_c + kk * D_OUT);
                ull zp;
                zp = pack2(za.x); FMA2(acc[0][0], zp, w2.x); FMA2(acc[0][1], zp, w2.y);
                zp = pack2(za.y); FMA2(acc[1][0], zp, w2.x); FMA2(acc[1][1], zp, w2.y);
                zp = pack2(za.z); FMA2(acc[2][0], zp, w2.x); FMA2(acc[2][1], zp, w2.y);
                zp = pack2(za.w); FMA2(acc[3][0], zp, w2.x); FMA2(acc[3][1], zp, w2.y);
                zp = pack2(zb.x); FMA2(acc[4][0], zp, w2.x); FMA2(acc[4][1], zp, w2.y);
                zp = pack2(zb.y); FMA2(acc[5][0], zp, w2.x); FMA2(acc[5][1], zp, w2.y);
                zp = pack2(zb.z); FMA2(acc[6][0], zp, w2.x); FMA2(acc[6][1], zp, w2.y);
                zp = pack2(zb.w); FMA2(acc[7][0], zp, w2.x); FMA2(acc[7][1], zp, w2.y);
            }
        }

        #pragma unroll
        for (int j = 0; j < 8; j++) {
            int node = node0 + ng * 8 + j;
            if (node < n_nodes) {
                float2 a = unpack2(acc[j][0]);
                float2 b = unpack2(acc[j][1]);
                __half2 h0 = __floats2half2_rn(a.x, a.y);
                __half2 h1 = __floats2half2_rn(b.x, b.y);
                uint2 v;
                v.x = *(unsigned*)&h0;
                v.y = *(unsigned*)&h1;
                *(uint2*)(g_y + (size_t)node * D_OUT + og * 4) = v;
            }
        }
    }
}

// ---------------------------------------------------------------------------
// CSR build: memset(g_cnt) -> histogram -> 3-kernel scan -> fill
// ---------------------------------------------------------------------------
extern "C" __global__ void rgcn_hist(const int* __restrict__ edst, int n_edges)
{
    int e = blockIdx.x * blockDim.x + threadIdx.x;
    if (e < n_edges) atomicAdd(&g_cnt[edst[e]], 1);
}

// Level 1: per-block sums over SCAN_PER-element chunks
extern "C" __global__ void __launch_bounds__(1024, 1)
rgcn_scan_part(int n_nodes)
{
    __shared__ int wtot[32];
    const int t = threadIdx.x, lane = t & 31, wid = t >> 5;
    int base = blockIdx.x * SCAN_PER + t * 4;
    int s = 0;
    #pragma unroll
    for (int j = 0; j < 4; j++) {
        int idx = base + j;
        if (idx < n_nodes) s += g_cnt[idx];
    }
    #pragma unroll
    for (int d = 16; d > 0; d >>= 1) s += __shfl_down_sync(0xffffffffu, s, d);
    if (lane == 0) wtot[wid] = s;
    __syncthreads();
    if (wid == 0) {
        int v = wtot[lane];
        #pragma unroll
        for (int d = 16; d > 0; d >>= 1) v += __shfl_down_sync(0xffffffffu, v, d);
        if (lane == 0) g_bsum[blockIdx.x] = v;
    }
}

// Level 2: one warp scans the block sums (exclusive)
extern "C" __global__ void rgcn_scan_tops(int nblocks)
{
    int t = threadIdx.x;
    int v = (t < nblocks) ? g_bsum[t] : 0;
    int s = v;
    #pragma unroll
    for (int d = 1; d < 32; d <<= 1) {
        int u = __shfl_up_sync(0xffffffffu, s, d);
        if (t >= d) s += u;
    }
    if (t < nblocks) g_bsum[t] = s - v;   // exclusive block offset
}

// Level 3: per-block element scan + global offset; writes g_start & cursors
extern "C" __global__ void __launch_bounds__(1024, 1)
rgcn_scan_final(int n_nodes)
{
    __shared__ int wtot[32];
    const int t = threadIdx.x, lane = t & 31, wid = t >> 5;
    int base = blockIdx.x * SCAN_PER + t * 4;
    int v[4];
    #pragma unroll
    for (int j = 0; j < 4; j++) {
        int idx = base + j;
        v[j] = (idx < n_nodes) ? g_cnt[idx] : 0;
    }
    int tsum = v[0] + v[1] + v[2] + v[3];
    int s = tsum;
    #pragma unroll
    for (int d = 1; d < 32; d <<= 1) {
        int u = __shfl_up_sync(0xffffffffu, s, d);
        if (lane >= d) s += u;
    }
    if (lane == 31) wtot[wid] = s;
    __syncthreads();
    if (wid == 0) {
        int wv = wtot[lane];
        #pragma unroll
        for (int d = 1; d < 32; d <<= 1) {
            int u = __shfl_up_sync(0xffffffffu, wv, d);
            if (lane >= d) wv += u;
        }
        wtot[lane] = wv;
    }
    __syncthreads();
    int off = g_bsum[blockIdx.x] + (wid ? wtot[wid - 1] : 0) + (s - tsum);
    #pragma unroll
    for (int j = 0; j < 4; j++) {
        int idx = base + j;
        if (idx < n_nodes) {
            g_start[idx] = off;
            g_cnt[idx]   = off;     // fill cursor
            if (idx == n_nodes - 1) g_start[n_nodes] = off + v[j];
            off += v[j];
        }
    }
}

extern "C" __global__ void rgcn_fill(const int*   __restrict__ esrc,
                                     const int*   __restrict__ edst,
                                     const float* __restrict__ ew,
                                     int n_edges)
{
    int e = blockIdx.x * blockDim.x + threadIdx.x;
    if (e >= n_edges) return;
    int d = edst[e];
    int pos = atomicAdd(&g_cnt[d], 1);
    g_elist[pos] = make_uint2((unsigned)esrc[e], __float_as_uint(ew[e]));
}

// ---------------------------------------------------------------------------
// Aggregate: one warp per dst node; each lane owns 2 outputs. No atomics.
// ---------------------------------------------------------------------------
__device__ __forceinline__ float2 yfrag(unsigned src, int lane)
{
    unsigned q = *((const unsigned*)g_y + ((size_t)src << 5) + lane);
    __half2 h; *(unsigned*)&h = q;
    return __half22float2(h);
}

extern "C" __global__ void __launch_bounds__(256, 8)
rgcn_aggregate(float* __restrict__ out, int n_nodes)
{
    int gid = blockIdx.x * blockDim.x + threadIdx.x;
    int n = gid >> 5;
    if (n >= n_nodes) return;
    int lane = gid & 31;
    int e  = g_start[n];
    int e1 = g_start[n + 1];
    float2 acc = make_float2(0.f, 0.f);

    for (; e + 4 <= e1; e += 4) {
        uint2 p0 = g_elist[e];
        uint2 p1 = g_elist[e + 1];
        uint2 p2 = g_elist[e + 2];
        uint2 p3 = g_elist[e + 3];
        float2 f0 = yfrag(p0.x, lane);
        float2 f1 = yfrag(p1.x, lane);
        float2 f2 = yfrag(p2.x, lane);
        float2 f3 = yfrag(p3.x, lane);
        float w0 = __uint_as_float(p0.y), w1 = __uint_as_float(p1.y);
        float w2 = __uint_as_float(p2.y), w3 = __uint_as_float(p3.y);
        acc.x += w0 * f0.x; acc.y += w0 * f0.y;
        acc.x += w1 * f1.x; acc.y += w1 * f1.y;
        acc.x += w2 * f2.x; acc.y += w2 * f2.y;
        acc.x += w3 * f3.x; acc.y += w3 * f3.y;
    }
    for (; e < e1; e++) {
        uint2 p = g_elist[e];
        float2 f = yfrag(p.x, lane);
        float w = __uint_as_float(p.y);
        acc.x += w * f.x; acc.y += w * f.y;
    }
    *(float2*)(out + (size_t)n * D_OUT + lane * 2) = acc;
}

// ---------------------------------------------------------------------------
extern "C" void kernel_launch(void* const* d_in, const int* in_sizes, int n_in,
                              void* d_out, int out_size)
{
    const float* x    = (const float*)d_in[0];
    const int*   esrc = (const int*)  d_in[1];
    const int*   edst = (const int*)  d_in[2];
    const float* ew   = (const float*)d_in[3];
    const float* wb   = (const float*)d_in[4];
    const float* wrel = (const float*)d_in[5];
    float* out = (float*)d_out;

    const int n_nodes = in_sizes[0] / (D_FEAT * N_REL);
    const int n_edges = in_sizes[1];
    const int n_tiles = (n_nodes + NODE_TILE - 1) / NODE_TILE;
    const int scan_blocks = (n_nodes + SCAN_PER - 1) / SCAN_PER;

    const int smem_bytes = K_DIM * D_OUT * sizeof(float)
                         + 2 * KC * NODE_TILE * sizeof(float)
                         + N_REL * 2 * sizeof(ull);
    cudaFuncSetAttribute(rgcn_transform,
                         cudaFuncAttributeMaxDynamicSharedMemorySize, smem_bytes);

    // zero counters via memset on the device symbol (no kernel)
    void* cnt_ptr = nullptr;
    cudaGetSymbolAddress(&cnt_ptr, g_cnt);
    cudaMemsetAsync(cnt_ptr, 0, (size_t)n_nodes * sizeof(int), 0);

    // node transform (independent of edges)
    rgcn_transform<<<296, TBLOCK, smem_bytes>>>(x, wb, wrel, n_nodes, n_tiles);

    // CSR build by dst
    rgcn_hist<<<(n_edges + 255) / 256, 256>>>(edst, n_edges);
    rgcn_scan_part<<<scan_blocks, 1024>>>(n_nodes);
    rgcn_scan_tops<<<1, 32>>>(scan_blocks);
    rgcn_scan_final<<<scan_blocks, 1024>>>(n_nodes);
    rgcn_fill<<<(n_edges + 255) / 256, 256>>>(esrc, edst, ew, n_edges);

    // gather-aggregate (writes every output element; no memset of out needed)
    int total_thr = n_nodes * 32;
    rgcn_aggregate<<<(total_thr + 255) / 256, 256>>>(out, n_nodes);
}

// round 8
// speedup vs baseline: 1.5667x; 1.3169x over previous
#include <cuda_runtime.h>
#include <cuda_fp16.h>
#include <mma.h>
#include <cstdint>

using namespace nvcuda;

#define N_NODES_MAX 50000
#define N_EDGES_MAX 800000
#define D_FEAT 64
#define D_OUT 64
#define N_REL 8
#define KTOT 512          /* k = i*8 + r (matches x row layout) */
#define KCH 64            /* K per chunk */
#define NCHUNKS (KTOT / KCH)
#define MTILE 128
#define TBLOCK 256
#define LDP 72            /* padded row stride in halves (144B, 16B-mult) */
#define SCAN_PER 4096

typedef unsigned long long ull;

// device scratch (static allocation per harness rules)
__device__ __half g_y[(size_t)N_NODES_MAX * D_OUT];   // 6.4 MB
__device__ __half g_wt[KTOT * LDP];                   // fused weights, padded rows
__device__ int    g_cnt[N_NODES_MAX];
__device__ int    g_start[N_NODES_MAX + 1];
__device__ uint2  g_elist[N_EDGES_MAX];
__device__ int    g_bsum[64];

// ---------------------------------------------------------------------------
// Wt build: Wt[k=i*8+r][o] = sum_b wrel[r,b] * wbases[b,i,o]  (fp16, padded)
// ---------------------------------------------------------------------------
extern "C" __global__ void rgcn_wt_build(const float* __restrict__ w_bases,
                                         const float* __restrict__ w_rel)
{
    int gid = blockIdx.x * blockDim.x + threadIdx.x;
    if (gid >= KTOT * D_OUT) return;
    int k = gid >> 6;          // 0..511
    int o = gid & 63;
    int i = k >> 3, r = k & 7;
    float acc = 0.f;
    #pragma unroll
    for (int b = 0; b < 4; b++)
        acc += w_rel[r * 4 + b] * w_bases[(b * D_FEAT + i) * D_OUT + o];
    g_wt[k * LDP + o] = __float2half_rn(acc);
}

// ---------------------------------------------------------------------------
// Transform via wmma (HMMA): y[node,o] = sum_k x[node,k] * Wt[k,o]
// Block: 128 nodes x 64 outs, 8 warps (16 nodes each), K=512 in 8 chunks.
// smem: wt_s [512][72] fp16 (73728B) | xb [2][128][72] fp16 (36864B)
//       epilogue reuses xb as float[128][64] staging.
// ---------------------------------------------------------------------------
extern "C" __global__ void __launch_bounds__(TBLOCK, 2)
rgcn_transform_mma(const float* __restrict__ x, int n_nodes)
{
    extern __shared__ __align__(16) char smem[];
    __half* wt_s = (__half*)smem;                       // 512*72 halves
    __half* xb   = (__half*)(smem + KTOT * LDP * 2);    // 2*128*72 halves

    const int t = threadIdx.x;
    const int warp = t >> 5;
    const int node0 = blockIdx.x * MTILE;

    // load Wt (73728 B linear copy)
    {
        const float4* src = (const float4*)g_wt;
        float4* dst = (float4*)wt_s;
        #pragma unroll
        for (int i2 = 0; i2 < 18; i2++) dst[t + i2 * TBLOCK] = src[t + i2 * TBLOCK];
    }

    wmma::fragment<wmma::accumulator, 16, 16, 16, float> facc[4];
    #pragma unroll
    for (int nt = 0; nt < 4; nt++) wmma::fill_fragment(facc[nt], 0.0f);

    for (int c = 0; c < NCHUNKS; c++) {
        __half* xcur = xb + (c & 1) * (MTILE * LDP);

        // convert x chunk [128 rows x 64 k] fp32 -> fp16 (rows padded to 72)
        #pragma unroll
        for (int it = 0; it < 8; it++) {
            int f   = t + it * TBLOCK;       // 0..2047
            int row = f >> 4;
            int c4  = f & 15;                // float4 within 64-k chunk row
            int node = node0 + row;
            uint2 st;
            if (node < n_nodes) {
                float4 v = ((const float4*)x)[(size_t)node * (KTOT / 4) + c * 16 + c4];
                __half2 h0 = __floats2half2_rn(v.x, v.y);
                __half2 h1 = __floats2half2_rn(v.z, v.w);
                st.x = *(uint32_t*)&h0;
                st.y = *(uint32_t*)&h1;
            } else {
                st.x = 0u; st.y = 0u;
            }
            *(uint2*)((char*)xcur + row * (LDP * 2) + c4 * 8) = st;
        }
        __syncthreads();   // conv(c) visible; also orders vs mma(c-1) readers

        const __half* xw = xcur + warp * 16 * LDP;
        #pragma unroll
        for (int kk = 0; kk < 4; kk++) {
            wmma::fragment<wmma::matrix_a, 16, 16, 16, __half, wmma::row_major> fa;
            wmma::load_matrix_sync(fa, xw + kk * 16, LDP);
            const __half* wrow = wt_s + (c * KCH + kk * 16) * LDP;
            #pragma unroll
            for (int nt = 0; nt < 4; nt++) {
                wmma::fragment<wmma::matrix_b, 16, 16, 16, __half, wmma::row_major> fb;
                wmma::load_matrix_sync(fb, wrow + nt * 16, LDP);
                wmma::mma_sync(facc[nt], fa, fb, facc[nt]);
            }
        }
    }

    // epilogue: stage fp32 result in smem (reuse xb), then write fp16 g_y
    __syncthreads();     // all mma reads of xb done
    float* stage = (float*)xb;       // 128*64 floats = 32768 B <= 36864 B
    #pragma unroll
    for (int nt = 0; nt < 4; nt++)
        wmma::store_matrix_sync(stage + (warp * 16) * D_OUT + nt * 16,
                                facc[nt], D_OUT, wmma::mem_row_major);
    __syncthreads();

    #pragma unroll
    for (int it = 0; it < 8; it++) {
        int f = t + it * TBLOCK;         // 0..2047
        int row = f >> 4;
        int q   = f & 15;                // uint2 (4 halves) within row
        int node = node0 + row;
        if (node < n_nodes) {
            float4 v = *(const float4*)(stage + row * D_OUT + q * 4);
            __half2 h0 = __floats2half2_rn(v.x, v.y);
            __half2 h1 = __floats2half2_rn(v.z, v.w);
            uint2 st;
            st.x = *(uint32_t*)&h0;
            st.y = *(uint32_t*)&h1;
            *(uint2*)(g_y + (size_t)node * D_OUT + q * 4) = st;
        }
    }
}

// ---------------------------------------------------------------------------
// CSR build: memset(g_cnt) -> histogram -> 3-kernel scan -> fill
// ---------------------------------------------------------------------------
extern "C" __global__ void rgcn_hist(const int* __restrict__ edst, int n_edges)
{
    int e = blockIdx.x * blockDim.x + threadIdx.x;
    if (e < n_edges) atomicAdd(&g_cnt[edst[e]], 1);
}

extern "C" __global__ void __launch_bounds__(1024, 1)
rgcn_scan_part(int n_nodes)
{
    __shared__ int wtot[32];
    const int t = threadIdx.x, lane = t & 31, wid = t >> 5;
    int base = blockIdx.x * SCAN_PER + t * 4;
    int s = 0;
    #pragma unroll
    for (int j = 0; j < 4; j++) {
        int idx = base + j;
        if (idx < n_nodes) s += g_cnt[idx];
    }
    #pragma unroll
    for (int d = 16; d > 0; d >>= 1) s += __shfl_down_sync(0xffffffffu, s, d);
    if (lane == 0) wtot[wid] = s;
    __syncthreads();
    if (wid == 0) {
        int v = wtot[lane];
        #pragma unroll
        for (int d = 16; d > 0; d >>= 1) v += __shfl_down_sync(0xffffffffu, v, d);
        if (lane == 0) g_bsum[blockIdx.x] = v;
    }
}

extern "C" __global__ void rgcn_scan_tops(int nblocks)
{
    int t = threadIdx.x;
    int v = (t < nblocks) ? g_bsum[t] : 0;
    int s = v;
    #pragma unroll
    for (int d = 1; d < 32; d <<= 1) {
        int u = __shfl_up_sync(0xffffffffu, s, d);
        if (t >= d) s += u;
    }
    if (t < nblocks) g_bsum[t] = s - v;
}

extern "C" __global__ void __launch_bounds__(1024, 1)
rgcn_scan_final(int n_nodes)
{
    __shared__ int wtot[32];
    const int t = threadIdx.x, lane = t & 31, wid = t >> 5;
    int base = blockIdx.x * SCAN_PER + t * 4;
    int v[4];
    #pragma unroll
    for (int j = 0; j < 4; j++) {
        int idx = base + j;
        v[j] = (idx < n_nodes) ? g_cnt[idx] : 0;
    }
    int tsum = v[0] + v[1] + v[2] + v[3];
    int s = tsum;
    #pragma unroll
    for (int d = 1; d < 32; d <<= 1) {
        int u = __shfl_up_sync(0xffffffffu, s, d);
        if (lane >= d) s += u;
    }
    if (lane == 31) wtot[wid] = s;
    __syncthreads();
    if (wid == 0) {
        int wv = wtot[lane];
        #pragma unroll
        for (int d = 1; d < 32; d <<= 1) {
            int u = __shfl_up_sync(0xffffffffu, wv, d);
            if (lane >= d) wv += u;
        }
        wtot[lane] = wv;
    }
    __syncthreads();
    int off = g_bsum[blockIdx.x] + (wid ? wtot[wid - 1] : 0) + (s - tsum);
    #pragma unroll
    for (int j = 0; j < 4; j++) {
        int idx = base + j;
        if (idx < n_nodes) {
            g_start[idx] = off;
            g_cnt[idx]   = off;
            if (idx == n_nodes - 1) g_start[n_nodes] = off + v[j];
            off += v[j];
        }
    }
}

extern "C" __global__ void rgcn_fill(const int*   __restrict__ esrc,
                                     const int*   __restrict__ edst,
                                     const float* __restrict__ ew,
                                     int n_edges)
{
    int e = blockIdx.x * blockDim.x + threadIdx.x;
    if (e >= n_edges) return;
    int d = edst[e];
    int pos = atomicAdd(&g_cnt[d], 1);
    g_elist[pos] = make_uint2((unsigned)esrc[e], __float_as_uint(ew[e]));
}

// ---------------------------------------------------------------------------
// Aggregate: one warp per dst node; each lane owns 2 outputs. No atomics.
// ---------------------------------------------------------------------------
__device__ __forceinline__ float2 yfrag(unsigned src, int lane)
{
    unsigned q = *((const unsigned*)g_y + ((size_t)src << 5) + lane);
    __half2 h; *(unsigned*)&h = q;
    return __half22float2(h);
}

extern "C" __global__ void __launch_bounds__(256, 8)
rgcn_aggregate(float* __restrict__ out, int n_nodes)
{
    int gid = blockIdx.x * blockDim.x + threadIdx.x;
    int n = gid >> 5;
    if (n >= n_nodes) return;
    int lane = gid & 31;
    int e  = g_start[n];
    int e1 = g_start[n + 1];
    float2 acc = make_float2(0.f, 0.f);

    for (; e + 4 <= e1; e += 4) {
        uint2 p0 = g_elist[e];
        uint2 p1 = g_elist[e + 1];
        uint2 p2 = g_elist[e + 2];
        uint2 p3 = g_elist[e + 3];
        float2 f0 = yfrag(p0.x, lane);
        float2 f1 = yfrag(p1.x, lane);
        float2 f2 = yfrag(p2.x, lane);
        float2 f3 = yfrag(p3.x, lane);
        float w0 = __uint_as_float(p0.y), w1 = __uint_as_float(p1.y);
        float w2 = __uint_as_float(p2.y), w3 = __uint_as_float(p3.y);
        acc.x += w0 * f0.x; acc.y += w0 * f0.y;
        acc.x += w1 * f1.x; acc.y += w1 * f1.y;
        acc.x += w2 * f2.x; acc.y += w2 * f2.y;
        acc.x += w3 * f3.x; acc.y += w3 * f3.y;
    }
    for (; e < e1; e++) {
        uint2 p = g_elist[e];
        float2 f = yfrag(p.x, lane);
        float w = __uint_as_float(p.y);
        acc.x += w * f.x; acc.y += w * f.y;
    }
    *(float2*)(out + (size_t)n * D_OUT + lane * 2) = acc;
}

// ---------------------------------------------------------------------------
extern "C" void kernel_launch(void* const* d_in, const int* in_sizes, int n_in,
                              void* d_out, int out_size)
{
    const float* x    = (const float*)d_in[0];
    const int*   esrc = (const int*)  d_in[1];
    const int*   edst = (const int*)  d_in[2];
    const float* ew   = (const float*)d_in[3];
    const float* wb   = (const float*)d_in[4];
    const float* wrel = (const float*)d_in[5];
    float* out = (float*)d_out;

    const int n_nodes = in_sizes[0] / (D_FEAT * N_REL);
    const int n_edges = in_sizes[1];
    const int n_tiles = (n_nodes + MTILE - 1) / MTILE;
    const int scan_blocks = (n_nodes + SCAN_PER - 1) / SCAN_PER;

    const int mma_smem = KTOT * LDP * 2 + 2 * MTILE * LDP * 2;   // 73728+36864=110592
    cudaFuncSetAttribute(rgcn_transform_mma,
                         cudaFuncAttributeMaxDynamicSharedMemorySize, mma_smem);

    // zero counters via memset on device symbol
    void* cnt_ptr = nullptr;
    cudaGetSymbolAddress(&cnt_ptr, g_cnt);
    cudaMemsetAsync(cnt_ptr, 0, (size_t)n_nodes * sizeof(int), 0);

    // fused weights, then HMMA transform
    rgcn_wt_build<<<(KTOT * D_OUT + 255) / 256, 256>>>(wb, wrel);
    rgcn_transform_mma<<<n_tiles, TBLOCK, mma_smem>>>(x, n_nodes);

    // CSR build by dst
    rgcn_hist<<<(n_edges + 255) / 256, 256>>>(edst, n_edges);
    rgcn_scan_part<<<scan_blocks, 1024>>>(n_nodes);
    rgcn_scan_tops<<<1, 32>>>(scan_blocks);
    rgcn_scan_final<<<scan_blocks, 1024>>>(n_nodes);
    rgcn_fill<<<(n_edges + 255) / 256, 256>>>(esrc, edst, ew, n_edges);

    // gather-aggregate
    int total_thr = n_nodes * 32;
    rgcn_aggregate<<<(total_thr + 255) / 256, 256>>>(out, n_nodes);
}

// round 9
// speedup vs baseline: 1.7990x; 1.1483x over previous
#include <cuda_runtime.h>
#include <cuda_fp16.h>
#include <mma.h>
#include <cstdint>

using namespace nvcuda;

#define N_NODES_MAX 50000
#define N_EDGES_MAX 800000
#define D_FEAT 64
#define D_OUT 64
#define N_REL 8
#define KTOT 512          /* k = i*8 + r (matches x row layout) */
#define KCH 64            /* K per chunk */
#define NCHUNKS (KTOT / KCH)
#define MTILE 128
#define TBLOCK 256
#define LDP 72            /* padded row stride in halves (144B) */
#define SCAN_PER 4096

typedef unsigned long long ull;

// device scratch (static allocation per harness rules)
__device__ __half g_y[(size_t)N_NODES_MAX * D_OUT];   // 6.4 MB
__device__ __half g_wt[KTOT * LDP];                   // fused weights, padded rows
__device__ int    g_cnt[N_NODES_MAX];
__device__ int    g_start[N_NODES_MAX + 1];
__device__ uint2  g_elist[N_EDGES_MAX];
__device__ volatile int g_sagg[16];
__device__ volatile int g_spre[16];
__device__ volatile int g_sflag[16];                  // 0=none 1=agg 2=prefix

// ---------------------------------------------------------------------------
// Wt build: Wt[k=i*8+r][o] = sum_b wrel[r,b] * wbases[b,i,o]  (fp16, padded)
// ---------------------------------------------------------------------------
extern "C" __global__ void rgcn_wt_build(const float* __restrict__ w_bases,
                                         const float* __restrict__ w_rel)
{
    int gid = blockIdx.x * blockDim.x + threadIdx.x;
    if (gid >= KTOT * D_OUT) return;
    int k = gid >> 6;
    int o = gid & 63;
    int i = k >> 3, r = k & 7;
    float acc = 0.f;
    #pragma unroll
    for (int b = 0; b < 4; b++)
        acc += w_rel[r * 4 + b] * w_bases[(b * D_FEAT + i) * D_OUT + o];
    g_wt[k * LDP + o] = __float2half_rn(acc);
}

// ---------------------------------------------------------------------------
// Transform via wmma (HMMA): y[node,o] = sum_k x[node,k] * Wt[k,o]
// ---------------------------------------------------------------------------
extern "C" __global__ void __launch_bounds__(TBLOCK, 2)
rgcn_transform_mma(const float* __restrict__ x, int n_nodes)
{
    extern __shared__ __align__(16) char smem[];
    __half* wt_s = (__half*)smem;                       // 512*72 halves
    __half* xb   = (__half*)(smem + KTOT * LDP * 2);    // 2*128*72 halves

    const int t = threadIdx.x;
    const int warp = t >> 5;
    const int node0 = blockIdx.x * MTILE;

    {
        const float4* src = (const float4*)g_wt;
        float4* dst = (float4*)wt_s;
        #pragma unroll
        for (int i2 = 0; i2 < 18; i2++) dst[t + i2 * TBLOCK] = src[t + i2 * TBLOCK];
    }

    wmma::fragment<wmma::accumulator, 16, 16, 16, float> facc[4];
    #pragma unroll
    for (int nt = 0; nt < 4; nt++) wmma::fill_fragment(facc[nt], 0.0f);

    for (int c = 0; c < NCHUNKS; c++) {
        __half* xcur = xb + (c & 1) * (MTILE * LDP);

        #pragma unroll
        for (int it = 0; it < 8; it++) {
            int f   = t + it * TBLOCK;
            int row = f >> 4;
            int c4  = f & 15;
            int node = node0 + row;
            uint2 st;
            if (node < n_nodes) {
                float4 v = ((const float4*)x)[(size_t)node * (KTOT / 4) + c * 16 + c4];
                __half2 h0 = __floats2half2_rn(v.x, v.y);
                __half2 h1 = __floats2half2_rn(v.z, v.w);
                st.x = *(uint32_t*)&h0;
                st.y = *(uint32_t*)&h1;
            } else {
                st.x = 0u; st.y = 0u;
            }
            *(uint2*)((char*)xcur + row * (LDP * 2) + c4 * 8) = st;
        }
        __syncthreads();

        const __half* xw = xcur + warp * 16 * LDP;
        #pragma unroll
        for (int kk = 0; kk < 4; kk++) {
            wmma::fragment<wmma::matrix_a, 16, 16, 16, __half, wmma::row_major> fa;
            wmma::load_matrix_sync(fa, xw + kk * 16, LDP);
            const __half* wrow = wt_s + (c * KCH + kk * 16) * LDP;
            #pragma unroll
            for (int nt = 0; nt < 4; nt++) {
                wmma::fragment<wmma::matrix_b, 16, 16, 16, __half, wmma::row_major> fb;
                wmma::load_matrix_sync(fb, wrow + nt * 16, LDP);
                wmma::mma_sync(facc[nt], fa, fb, facc[nt]);
            }
        }
    }

    __syncthreads();
    float* stage = (float*)xb;
    #pragma unroll
    for (int nt = 0; nt < 4; nt++)
        wmma::store_matrix_sync(stage + (warp * 16) * D_OUT + nt * 16,
                                facc[nt], D_OUT, wmma::mem_row_major);
    __syncthreads();

    #pragma unroll
    for (int it = 0; it < 8; it++) {
        int f = t + it * TBLOCK;
        int row = f >> 4;
        int q   = f & 15;
        int node = node0 + row;
        if (node < n_nodes) {
            float4 v = *(const float4*)(stage + row * D_OUT + q * 4);
            __half2 h0 = __floats2half2_rn(v.x, v.y);
            __half2 h1 = __floats2half2_rn(v.z, v.w);
            uint2 st;
            st.x = *(uint32_t*)&h0;
            st.y = *(uint32_t*)&h1;
            *(uint2*)(g_y + (size_t)node * D_OUT + q * 4) = st;
        }
    }
}

// ---------------------------------------------------------------------------
// CSR build: memset(g_cnt,g_sflag) -> hist -> fused lookback scan -> fill
// ---------------------------------------------------------------------------
extern "C" __global__ void rgcn_hist(const int* __restrict__ edst, int n_edges)
{
    int e = blockIdx.x * blockDim.x + threadIdx.x;
    if (e < n_edges) atomicAdd(&g_cnt[edst[e]], 1);
}

// single-pass scan, grid <= 16 blocks (all resident), decoupled lookback
extern "C" __global__ void __launch_bounds__(1024, 1)
rgcn_scan_fused(int n_nodes)
{
    __shared__ int wtot[32];
    __shared__ int blk_prefix;
    const int t = threadIdx.x, lane = t & 31, wid = t >> 5;
    const int b = blockIdx.x;
    int base = b * SCAN_PER + t * 4;
    int v[4];
    #pragma unroll
    for (int j = 0; j < 4; j++) {
        int idx = base + j;
        v[j] = (idx < n_nodes) ? g_cnt[idx] : 0;
    }
    int tsum = v[0] + v[1] + v[2] + v[3];
    int s = tsum;
    #pragma unroll
    for (int d = 1; d < 32; d <<= 1) {
        int u = __shfl_up_sync(0xffffffffu, s, d);
        if (lane >= d) s += u;
    }
    if (lane == 31) wtot[wid] = s;
    __syncthreads();
    if (wid == 0) {
        int wv = wtot[lane];
        #pragma unroll
        for (int d = 1; d < 32; d <<= 1) {
            int u = __shfl_up_sync(0xffffffffu, wv, d);
            if (lane >= d) wv += u;
        }
        wtot[lane] = wv;
    }
    __syncthreads();
    int local_excl = (s - tsum) + (wid ? wtot[wid - 1] : 0);
    int block_total = wtot[31];

    if (t == 0) {
        if (b == 0) {
            g_spre[0] = block_total;
            __threadfence();
            g_sflag[0] = 2;
            blk_prefix = 0;
        } else {
            g_sagg[b] = block_total;
            __threadfence();
            g_sflag[b] = 1;
            int run = 0;
            for (int j = b - 1; j >= 0; ) {
                int f;
                do { f = g_sflag[j]; } while (f == 0);
                if (f == 2) { run += g_spre[j]; break; }
                run += g_sagg[j];
                j--;
            }
            blk_prefix = run;
            g_spre[b] = run + block_total;
            __threadfence();
            g_sflag[b] = 2;
        }
    }
    __syncthreads();

    int off = blk_prefix + local_excl;
    #pragma unroll
    for (int j = 0; j < 4; j++) {
        int idx = base + j;
        if (idx < n_nodes) {
            g_start[idx] = off;
            g_cnt[idx]   = off;
            if (idx == n_nodes - 1) g_start[n_nodes] = off + v[j];
            off += v[j];
        }
    }
}

extern "C" __global__ void rgcn_fill(const int*   __restrict__ esrc,
                                     const int*   __restrict__ edst,
                                     const float* __restrict__ ew,
                                     int n_edges)
{
    int e = blockIdx.x * blockDim.x + threadIdx.x;
    if (e >= n_edges) return;
    int d = edst[e];
    int pos = atomicAdd(&g_cnt[d], 1);
    g_elist[pos] = make_uint2((unsigned)esrc[e], __float_as_uint(ew[e]));
}

// ---------------------------------------------------------------------------
// Aggregate: one warp per dst node; each lane owns 2 outputs. No atomics.
// ---------------------------------------------------------------------------
__device__ __forceinline__ float2 yfrag(unsigned src, int lane)
{
    unsigned q = *((const unsigned*)g_y + ((size_t)src << 5) + lane);
    __half2 h; *(unsigned*)&h = q;
    return __half22float2(h);
}

extern "C" __global__ void __launch_bounds__(256, 8)
rgcn_aggregate(float* __restrict__ out, int n_nodes)
{
    int gid = blockIdx.x * blockDim.x + threadIdx.x;
    int n = gid >> 5;
    if (n >= n_nodes) return;
    int lane = gid & 31;
    int e  = g_start[n];
    int e1 = g_start[n + 1];
    float2 acc = make_float2(0.f, 0.f);

    for (; e + 4 <= e1; e += 4) {
        uint2 p0 = g_elist[e];
        uint2 p1 = g_elist[e + 1];
        uint2 p2 = g_elist[e + 2];
        uint2 p3 = g_elist[e + 3];
        float2 f0 = yfrag(p0.x, lane);
        float2 f1 = yfrag(p1.x, lane);
        float2 f2 = yfrag(p2.x, lane);
        float2 f3 = yfrag(p3.x, lane);
        float w0 = __uint_as_float(p0.y), w1 = __uint_as_float(p1.y);
        float w2 = __uint_as_float(p2.y), w3 = __uint_as_float(p3.y);
        acc.x += w0 * f0.x; acc.y += w0 * f0.y;
        acc.x += w1 * f1.x; acc.y += w1 * f1.y;
        acc.x += w2 * f2.x; acc.y += w2 * f2.y;
        acc.x += w3 * f3.x; acc.y += w3 * f3.y;
    }
    for (; e < e1; e++) {
        uint2 p = g_elist[e];
        float2 f = yfrag(p.x, lane);
        float w = __uint_as_float(p.y);
        acc.x += w * f.x; acc.y += w * f.y;
    }
    *(float2*)(out + (size_t)n * D_OUT + lane * 2) = acc;
}

// ---------------------------------------------------------------------------
extern "C" void kernel_launch(void* const* d_in, const int* in_sizes, int n_in,
                              void* d_out, int out_size)
{
    const float* x    = (const float*)d_in[0];
    const int*   esrc = (const int*)  d_in[1];
    const int*   edst = (const int*)  d_in[2];
    const float* ew   = (const float*)d_in[3];
    const float* wb   = (const float*)d_in[4];
    const float* wrel = (const float*)d_in[5];
    float* out = (float*)d_out;

    const int n_nodes = in_sizes[0] / (D_FEAT * N_REL);
    const int n_edges = in_sizes[1];
    const int n_tiles = (n_nodes + MTILE - 1) / MTILE;
    const int scan_blocks = (n_nodes + SCAN_PER - 1) / SCAN_PER;

    const int mma_smem = KTOT * LDP * 2 + 2 * MTILE * LDP * 2;   // 110592
    cudaFuncSetAttribute(rgcn_transform_mma,
                         cudaFuncAttributeMaxDynamicSharedMemorySize, mma_smem);

    // fork stream + events (created per call; host cost is outside graph replay)
    cudaStream_t s1;
    cudaStreamCreateWithFlags(&s1, cudaStreamNonBlocking);
    cudaEvent_t evFork, evJoin;
    cudaEventCreateWithFlags(&evFork, cudaEventDisableTiming);
    cudaEventCreateWithFlags(&evJoin, cudaEventDisableTiming);

    // branch A (s1): weights + HMMA transform
    cudaEventRecord(evFork, 0);
    cudaStreamWaitEvent(s1, evFork, 0);
    rgcn_wt_build<<<(KTOT * D_OUT + 255) / 256, 256, 0, s1>>>(wb, wrel);
    rgcn_transform_mma<<<n_tiles, TBLOCK, mma_smem, s1>>>(x, n_nodes);
    cudaEventRecord(evJoin, s1);

    // branch B (main): CSR build by dst
    void* cnt_ptr = nullptr;
    cudaGetSymbolAddress(&cnt_ptr, g_cnt);
    cudaMemsetAsync(cnt_ptr, 0, (size_t)n_nodes * sizeof(int), 0);
    void* flag_ptr = nullptr;
    cudaGetSymbolAddress(&flag_ptr, (const void*)g_sflag);
    cudaMemsetAsync(flag_ptr, 0, 16 * sizeof(int), 0);

    rgcn_hist<<<(n_edges + 255) / 256, 256>>>(edst, n_edges);
    rgcn_scan_fused<<<scan_blocks, 1024>>>(n_nodes);
    rgcn_fill<<<(n_edges + 255) / 256, 256>>>(esrc, edst, ew, n_edges);

    // join, then gather-aggregate
    cudaStreamWaitEvent(0, evJoin, 0);
    int total_thr = n_nodes * 32;
    rgcn_aggregate<<<(total_thr + 255) / 256, 256>>>(out, n_nodes);
}

// round 10
// speedup vs baseline: 1.9388x; 1.0777x over previous
#include <cuda_runtime.h>
#include <cuda_fp16.h>
#include <mma.h>
#include <cstdint>

using namespace nvcuda;

#define N_NODES_MAX 50000
#define N_EDGES_MAX 800000
#define D_FEAT 64
#define D_OUT 64
#define N_REL 8
#define KTOT 512          /* k = i*8 + r (matches x row layout) */
#define KCH 64            /* K per chunk */
#define NCHUNKS (KTOT / KCH)
#define MTILE 128
#define TBLOCK 256
#define LDP 72            /* padded row stride in halves (144B) */
#define SCAN_PER 4096
#define TGRID 296         /* persistent transform grid: 2 blocks/SM x 148 */

typedef unsigned long long ull;

// device scratch (static allocation per harness rules)
__device__ __half g_y[(size_t)N_NODES_MAX * D_OUT];   // 6.4 MB
__device__ __half g_wt[KTOT * LDP];                   // fused weights, padded rows
__device__ int    g_cnt[N_NODES_MAX + 64];            // counts/cursors + scan pub tail
__device__ int    g_start[N_NODES_MAX + 1];
__device__ uint2  g_elist[N_EDGES_MAX];

// ---------------------------------------------------------------------------
// Wt build: Wt[k=i*8+r][o] = sum_b wrel[r,b] * wbases[b,i,o]  (fp16, padded)
// ---------------------------------------------------------------------------
extern "C" __global__ void rgcn_wt_build(const float* __restrict__ w_bases,
                                         const float* __restrict__ w_rel)
{
    int gid = blockIdx.x * blockDim.x + threadIdx.x;
    if (gid >= KTOT * D_OUT) return;
    int k = gid >> 6;
    int o = gid & 63;
    int i = k >> 3, r = k & 7;
    float acc = 0.f;
    #pragma unroll
    for (int b = 0; b < 4; b++)
        acc += w_rel[r * 4 + b] * w_bases[(b * D_FEAT + i) * D_OUT + o];
    g_wt[k * LDP + o] = __float2half_rn(acc);
}

// ---------------------------------------------------------------------------
// Transform via wmma (HMMA), persistent grid: y[node,o] = sum_k x[node,k]*Wt[k,o]
// ---------------------------------------------------------------------------
extern "C" __global__ void __launch_bounds__(TBLOCK, 2)
rgcn_transform_mma(const float* __restrict__ x, int n_nodes, int n_tiles)
{
    extern __shared__ __align__(16) char smem[];
    __half* wt_s = (__half*)smem;                       // 512*72 halves
    __half* xb   = (__half*)(smem + KTOT * LDP * 2);    // 2*128*72 halves

    const int t = threadIdx.x;
    const int warp = t >> 5;

    {
        const float4* src = (const float4*)g_wt;
        float4* dst = (float4*)wt_s;
        #pragma unroll
        for (int i2 = 0; i2 < 18; i2++) dst[t + i2 * TBLOCK] = src[t + i2 * TBLOCK];
    }

    for (int tile = blockIdx.x; tile < n_tiles; tile += gridDim.x) {
        const int node0 = tile * MTILE;

        wmma::fragment<wmma::accumulator, 16, 16, 16, float> facc[4];
        #pragma unroll
        for (int nt = 0; nt < 4; nt++) wmma::fill_fragment(facc[nt], 0.0f);

        for (int c = 0; c < NCHUNKS; c++) {
            __half* xcur = xb + (c & 1) * (MTILE * LDP);

            #pragma unroll
            for (int it = 0; it < 8; it++) {
                int f   = t + it * TBLOCK;
                int row = f >> 4;
                int c4  = f & 15;
                int node = node0 + row;
                uint2 st;
                if (node < n_nodes) {
                    float4 v = ((const float4*)x)[(size_t)node * (KTOT / 4) + c * 16 + c4];
                    __half2 h0 = __floats2half2_rn(v.x, v.y);
                    __half2 h1 = __floats2half2_rn(v.z, v.w);
                    st.x = *(uint32_t*)&h0;
                    st.y = *(uint32_t*)&h1;
                } else {
                    st.x = 0u; st.y = 0u;
                }
                *(uint2*)((char*)xcur + row * (LDP * 2) + c4 * 8) = st;
            }
            __syncthreads();   // conv(c) visible; also orders vs mma(c-1) readers

            const __half* xw = xcur + warp * 16 * LDP;
            #pragma unroll
            for (int kk = 0; kk < 4; kk++) {
                wmma::fragment<wmma::matrix_a, 16, 16, 16, __half, wmma::row_major> fa;
                wmma::load_matrix_sync(fa, xw + kk * 16, LDP);
                const __half* wrow = wt_s + (c * KCH + kk * 16) * LDP;
                #pragma unroll
                for (int nt = 0; nt < 4; nt++) {
                    wmma::fragment<wmma::matrix_b, 16, 16, 16, __half, wmma::row_major> fb;
                    wmma::load_matrix_sync(fb, wrow + nt * 16, LDP);
                    wmma::mma_sync(facc[nt], fa, fb, facc[nt]);
                }
            }
        }

        __syncthreads();     // last-chunk mma reads of xb done
        float* stage = (float*)xb;
        #pragma unroll
        for (int nt = 0; nt < 4; nt++)
            wmma::store_matrix_sync(stage + (warp * 16) * D_OUT + nt * 16,
                                    facc[nt], D_OUT, wmma::mem_row_major);
        __syncthreads();

        #pragma unroll
        for (int it = 0; it < 8; it++) {
            int f = t + it * TBLOCK;
            int row = f >> 4;
            int q   = f & 15;
            int node = node0 + row;
            if (node < n_nodes) {
                float4 v = *(const float4*)(stage + row * D_OUT + q * 4);
                __half2 h0 = __floats2half2_rn(v.x, v.y);
                __half2 h1 = __floats2half2_rn(v.z, v.w);
                uint2 st;
                st.x = *(uint32_t*)&h0;
                st.y = *(uint32_t*)&h1;
                *(uint2*)(g_y + (size_t)node * D_OUT + q * 4) = st;
            }
        }
        __syncthreads();     // stage reads done before next tile's conv writes
    }
}

// ---------------------------------------------------------------------------
// CSR build: one memset(g_cnt incl. pub tail) -> hist -> fused scan -> fill
// ---------------------------------------------------------------------------
extern "C" __global__ void rgcn_hist(const int* __restrict__ edst, int n_edges)
{
    int e = blockIdx.x * blockDim.x + threadIdx.x;
    if (e < n_edges) atomicAdd(&g_cnt[edst[e]], 1);
}

// single-pass scan, grid <= 16 blocks, PARALLEL publish/poll (no serial chain)
extern "C" __global__ void __launch_bounds__(1024, 1)
rgcn_scan_fused(int n_nodes)
{
    __shared__ int wtot[32];
    __shared__ int preds[16];
    __shared__ int bp_sh;
    const int t = threadIdx.x, lane = t & 31, wid = t >> 5;
    const int b = blockIdx.x;
    volatile ull* pub = (volatile ull*)(g_cnt + ((n_nodes + 1) & ~1));

    int base = b * SCAN_PER + t * 4;
    int v[4];
    #pragma unroll
    for (int j = 0; j < 4; j++) {
        int idx = base + j;
        v[j] = (idx < n_nodes) ? g_cnt[idx] : 0;
    }
    int tsum = v[0] + v[1] + v[2] + v[3];
    int s = tsum;
    #pragma unroll
    for (int d = 1; d < 32; d <<= 1) {
        int u = __shfl_up_sync(0xffffffffu, s, d);
        if (lane >= d) s += u;
    }
    if (lane == 31) wtot[wid] = s;
    __syncthreads();
    if (wid == 0) {
        int wv = wtot[lane];
        #pragma unroll
        for (int d = 1; d < 32; d <<= 1) {
            int u = __shfl_up_sync(0xffffffffu, wv, d);
            if (lane >= d) wv += u;
        }
        wtot[lane] = wv;
    }
    __syncthreads();
    int local_excl = (s - tsum) + (wid ? wtot[wid - 1] : 0);
    int block_total = wtot[31];

    // publish own total as a single 64-bit word (ready bit | value)
    if (t == 0)
        pub[b] = (1ULL << 32) | (unsigned)block_total;
    // poll ALL predecessors concurrently
    if (t < b) {
        ull pv;
        do { pv = pub[t]; } while ((pv >> 32) == 0);
        preds[t] = (int)(unsigned)pv;
    }
    __syncthreads();
    if (t == 0) {
        int r = 0;
        for (int j = 0; j < b; j++) r += preds[j];
        bp_sh = r;
    }
    __syncthreads();

    int off = bp_sh + local_excl;
    #pragma unroll
    for (int j = 0; j < 4; j++) {
        int idx = base + j;
        if (idx < n_nodes) {
            g_start[idx] = off;
            g_cnt[idx]   = off;
            if (idx == n_nodes - 1) g_start[n_nodes] = off + v[j];
            off += v[j];
        }
    }
}

extern "C" __global__ void rgcn_fill(const int*   __restrict__ esrc,
                                     const int*   __restrict__ edst,
                                     const float* __restrict__ ew,
                                     int n_edges)
{
    int e = blockIdx.x * blockDim.x + threadIdx.x;
    if (e >= n_edges) return;
    int d = edst[e];
    int pos = atomicAdd(&g_cnt[d], 1);
    g_elist[pos] = make_uint2((unsigned)esrc[e], __float_as_uint(ew[e]));
}

// ---------------------------------------------------------------------------
// Aggregate: one warp per dst node; each lane owns 2 outputs. No atomics.
// ---------------------------------------------------------------------------
__device__ __forceinline__ float2 yfrag(unsigned src, int lane)
{
    unsigned q = *((const unsigned*)g_y + ((size_t)src << 5) + lane);
    __half2 h; *(unsigned*)&h = q;
    return __half22float2(h);
}

extern "C" __global__ void __launch_bounds__(256, 8)
rgcn_aggregate(float* __restrict__ out, int n_nodes)
{
    int gid = blockIdx.x * blockDim.x + threadIdx.x;
    int n = gid >> 5;
    if (n >= n_nodes) return;
    int lane = gid & 31;
    int e  = g_start[n];
    int e1 = g_start[n + 1];
    float2 acc = make_float2(0.f, 0.f);

    for (; e + 8 <= e1; e += 8) {
        uint2 p[8];
        #pragma unroll
        for (int j = 0; j < 8; j++) p[j] = g_elist[e + j];
        float2 f[8];
        #pragma unroll
        for (int j = 0; j < 8; j++) f[j] = yfrag(p[j].x, lane);
        #pragma unroll
        for (int j = 0; j < 8; j++) {
            float w = __uint_as_float(p[j].y);
            acc.x += w * f[j].x;
            acc.y += w * f[j].y;
        }
    }
    if (e + 4 <= e1) {
        uint2 p[4];
        #pragma unroll
        for (int j = 0; j < 4; j++) p[j] = g_elist[e + j];
        float2 f[4];
        #pragma unroll
        for (int j = 0; j < 4; j++) f[j] = yfrag(p[j].x, lane);
        #pragma unroll
        for (int j = 0; j < 4; j++) {
            float w = __uint_as_float(p[j].y);
            acc.x += w * f[j].x;
            acc.y += w * f[j].y;
        }
        e += 4;
    }
    for (; e < e1; e++) {
        uint2 p = g_elist[e];
        float2 f = yfrag(p.x, lane);
        float w = __uint_as_float(p.y);
        acc.x += w * f.x;
        acc.y += w * f.y;
    }
    *(float2*)(out + (size_t)n * D_OUT + lane * 2) = acc;
}

// ---------------------------------------------------------------------------
extern "C" void kernel_launch(void* const* d_in, const int* in_sizes, int n_in,
                              void* d_out, int out_size)
{
    const float* x    = (const float*)d_in[0];
    const int*   esrc = (const int*)  d_in[1];
    const int*   edst = (const int*)  d_in[2];
    const float* ew   = (const float*)d_in[3];
    const float* wb   = (const float*)d_in[4];
    const float* wrel = (const float*)d_in[5];
    float* out = (float*)d_out;

    const int n_nodes = in_sizes[0] / (D_FEAT * N_REL);
    const int n_edges = in_sizes[1];
    const int n_tiles = (n_nodes + MTILE - 1) / MTILE;
    const int scan_blocks = (n_nodes + SCAN_PER - 1) / SCAN_PER;

    const int mma_smem = KTOT * LDP * 2 + 2 * MTILE * LDP * 2;   // 110592
    cudaFuncSetAttribute(rgcn_transform_mma,
                         cudaFuncAttributeMaxDynamicSharedMemorySize, mma_smem);

    // fork stream + events (host-side; outside graph replay cost)
    cudaStream_t s1;
    cudaStreamCreateWithFlags(&s1, cudaStreamNonBlocking);
    cudaEvent_t evFork, evJoin;
    cudaEventCreateWithFlags(&evFork, cudaEventDisableTiming);
    cudaEventCreateWithFlags(&evJoin, cudaEventDisableTiming);

    // branch A (s1): weights + HMMA transform (persistent grid)
    cudaEventRecord(evFork, 0);
    cudaStreamWaitEvent(s1, evFork, 0);
    rgcn_wt_build<<<(KTOT * D_OUT + 255) / 256, 256, 0, s1>>>(wb, wrel);
    int tgrid = n_tiles < TGRID ? n_tiles : TGRID;
    rgcn_transform_mma<<<tgrid, TBLOCK, mma_smem, s1>>>(x, n_nodes, n_tiles);
    cudaEventRecord(evJoin, s1);

    // branch B (main): CSR build by dst. One memset covers counters + pub tail.
    void* cnt_ptr = nullptr;
    cudaGetSymbolAddress(&cnt_ptr, g_cnt);
    size_t zero_bytes = (size_t)(((n_nodes + 1) & ~1) + 32) * sizeof(int);
    cudaMemsetAsync(cnt_ptr, 0, zero_bytes, 0);

    rgcn_hist<<<(n_edges + 255) / 256, 256>>>(edst, n_edges);
    rgcn_scan_fused<<<scan_blocks, 1024>>>(n_nodes);
    rgcn_fill<<<(n_edges + 255) / 256, 256>>>(esrc, edst, ew, n_edges);

    // join, then gather-aggregate
    cudaStreamWaitEvent(0, evJoin, 0);
    int total_thr = n_nodes * 32;
    rgcn_aggregate<<<(total_thr + 255) / 256, 256>>>(out, n_nodes);
}

// round 11
// speedup vs baseline: 2.0939x; 1.0800x over previous
#include <cuda_runtime.h>
#include <cuda_fp16.h>
#include <mma.h>
#include <cstdint>

using namespace nvcuda;

#define N_NODES_MAX 50000
#define N_EDGES_MAX 800000
#define D_FEAT 64
#define D_OUT 64
#define N_REL 8
#define KTOT 512          /* k = i*8 + r (matches x row layout) */
#define KCH 64            /* K per chunk */
#define NCHUNKS (KTOT / KCH)
#define MTILE 128
#define TBLOCK 256
#define LDP 72            /* padded row stride in halves (144B) */
#define SCAN_PER 4096
#define TGRID 296         /* transform grid: 2 blocks/SM x 148 */

typedef unsigned long long ull;

// device scratch (static allocation per harness rules)
__device__ __half   g_y[(size_t)N_NODES_MAX * D_OUT];   // 6.4 MB
__device__ __half   g_wt[KTOT * LDP];                   // fused weights, padded
__device__ int      g_cnt[N_NODES_MAX + 64];            // counts/cursors + scan pub tail
__device__ int      g_start[N_NODES_MAX + 1];
__device__ uint32_t g_elist[N_EDGES_MAX];               // src:16 | half(w):16
__device__ int      g_tilectr;                          // dynamic tile counter

// ---------------------------------------------------------------------------
// Wt build + tile-counter init
// ---------------------------------------------------------------------------
extern "C" __global__ void rgcn_wt_build(const float* __restrict__ w_bases,
                                         const float* __restrict__ w_rel,
                                         int tgrid)
{
    int gid = blockIdx.x * blockDim.x + threadIdx.x;
    if (gid == 0) g_tilectr = tgrid;     // same stream as transform: ordered
    if (gid >= KTOT * D_OUT) return;
    int k = gid >> 6;
    int o = gid & 63;
    int i = k >> 3, r = k & 7;
    float acc = 0.f;
    #pragma unroll
    for (int b = 0; b < 4; b++)
        acc += w_rel[r * 4 + b] * w_bases[(b * D_FEAT + i) * D_OUT + o];
    g_wt[k * LDP + o] = __float2half_rn(acc);
}

// ---------------------------------------------------------------------------
// Transform via wmma (HMMA), dynamic tiles, software-pipelined conv:
//   y[node,o] = sum_k x[node,k] * Wt[k,o]
// ---------------------------------------------------------------------------
extern "C" __global__ void __launch_bounds__(TBLOCK, 2)
rgcn_transform_mma(const float* __restrict__ x, int n_nodes, int n_tiles)
{
    extern __shared__ __align__(16) char smem[];
    __half* wt_s = (__half*)smem;                       // 512*72 halves
    __half* xb   = (__half*)(smem + KTOT * LDP * 2);    // 2*128*72 halves

    const int t = threadIdx.x;
    const int warp = t >> 5;

    {
        const float4* src = (const float4*)g_wt;
        float4* dst = (float4*)wt_s;
        #pragma unroll
        for (int i2 = 0; i2 < 18; i2++) dst[t + i2 * TBLOCK] = src[t + i2 * TBLOCK];
    }
    // wt_s visible by the first in-loop __syncthreads() before any mma.

    int tile = blockIdx.x;
    while (tile < n_tiles) {
        const int node0 = tile * MTILE;

        wmma::fragment<wmma::accumulator, 16, 16, 16, float> facc[4];
        #pragma unroll
        for (int nt = 0; nt < 4; nt++) wmma::fill_fragment(facc[nt], 0.0f);

        // prefetch chunk 0 into registers
        float4 pf[8];
        #pragma unroll
        for (int it = 0; it < 8; it++) {
            int f = t + it * TBLOCK;
            int row = f >> 4, c4 = f & 15;
            int node = node0 + row;
            pf[it] = (node < n_nodes)
                ? ((const float4*)x)[(size_t)node * (KTOT / 4) + c4]
                : make_float4(0.f, 0.f, 0.f, 0.f);
        }

        for (int c = 0; c < NCHUNKS; c++) {
            __half* xcur = xb + (c & 1) * (MTILE * LDP);

            // cvt + store prefetched chunk c
            #pragma unroll
            for (int it = 0; it < 8; it++) {
                int f = t + it * TBLOCK;
                int row = f >> 4, c4 = f & 15;
                __half2 h0 = __floats2half2_rn(pf[it].x, pf[it].y);
                __half2 h1 = __floats2half2_rn(pf[it].z, pf[it].w);
                uint2 st;
                st.x = *(uint32_t*)&h0;
                st.y = *(uint32_t*)&h1;
                *(uint2*)((char*)xcur + row * (LDP * 2) + c4 * 8) = st;
            }
            __syncthreads();   // conv(c) visible; mma(c-1) readers of other buf done

            // prefetch chunk c+1 (overlaps with mma below)
            if (c + 1 < NCHUNKS) {
                #pragma unroll
                for (int it = 0; it < 8; it++) {
                    int f = t + it * TBLOCK;
                    int row = f >> 4, c4 = f & 15;
                    int node = node0 + row;
                    pf[it] = (node < n_nodes)
                        ? ((const float4*)x)[(size_t)node * (KTOT / 4) + (c + 1) * 16 + c4]
                        : make_float4(0.f, 0.f, 0.f, 0.f);
                }
            }

            const __half* xw = xcur + warp * 16 * LDP;
            #pragma unroll
            for (int kk = 0; kk < 4; kk++) {
                wmma::fragment<wmma::matrix_a, 16, 16, 16, __half, wmma::row_major> fa;
                wmma::load_matrix_sync(fa, xw + kk * 16, LDP);
                const __half* wrow = wt_s + (c * KCH + kk * 16) * LDP;
                #pragma unroll
                for (int nt = 0; nt < 4; nt++) {
                    wmma::fragment<wmma::matrix_b, 16, 16, 16, __half, wmma::row_major> fb;
                    wmma::load_matrix_sync(fb, wrow + nt * 16, LDP);
                    wmma::mma_sync(facc[nt], fa, fb, facc[nt]);
                }
            }
        }

        __syncthreads();     // all mma reads of xb done (stage spans both bufs)
        float* stage = (float*)xb;
        #pragma unroll
        for (int nt = 0; nt < 4; nt++)
            wmma::store_matrix_sync(stage + (warp * 16) * D_OUT + nt * 16,
                                    facc[nt], D_OUT, wmma::mem_row_major);
        __syncthreads();

        #pragma unroll
        for (int it = 0; it < 8; it++) {
            int f = t + it * TBLOCK;
            int row = f >> 4, q = f & 15;
            int node = node0 + row;
            if (node < n_nodes) {
                float4 v = *(const float4*)(stage + row * D_OUT + q * 4);
                __half2 h0 = __floats2half2_rn(v.x, v.y);
                __half2 h1 = __floats2half2_rn(v.z, v.w);
                uint2 st;
                st.x = *(uint32_t*)&h0;
                st.y = *(uint32_t*)&h1;
                *(uint2*)(g_y + (size_t)node * D_OUT + q * 4) = st;
            }
        }
        __syncthreads();     // stage reads done before next tile's conv writes

        if (t == 0) ((int*)xb)[0] = atomicAdd(&g_tilectr, 1);
        __syncthreads();
        tile = ((int*)xb)[0];
        __syncthreads();
    }
}

// ---------------------------------------------------------------------------
// CSR build: one memset(g_cnt incl. pub tail) -> hist -> fused scan -> fill
// ---------------------------------------------------------------------------
extern "C" __global__ void rgcn_hist(const int* __restrict__ edst, int n_edges)
{
    int e = blockIdx.x * blockDim.x + threadIdx.x;
    if (e < n_edges) atomicAdd(&g_cnt[edst[e]], 1);
}

// single-pass scan, grid <= 16 blocks, parallel publish/poll
extern "C" __global__ void __launch_bounds__(1024, 1)
rgcn_scan_fused(int n_nodes)
{
    __shared__ int wtot[32];
    __shared__ int preds[16];
    __shared__ int bp_sh;
    const int t = threadIdx.x, lane = t & 31, wid = t >> 5;
    const int b = blockIdx.x;
    volatile ull* pub = (volatile ull*)(g_cnt + ((n_nodes + 1) & ~1));

    int base = b * SCAN_PER + t * 4;
    int v[4];
    #pragma unroll
    for (int j = 0; j < 4; j++) {
        int idx = base + j;
        v[j] = (idx < n_nodes) ? g_cnt[idx] : 0;
    }
    int tsum = v[0] + v[1] + v[2] + v[3];
    int s = tsum;
    #pragma unroll
    for (int d = 1; d < 32; d <<= 1) {
        int u = __shfl_up_sync(0xffffffffu, s, d);
        if (lane >= d) s += u;
    }
    if (lane == 31) wtot[wid] = s;
    __syncthreads();
    if (wid == 0) {
        int wv = wtot[lane];
        #pragma unroll
        for (int d = 1; d < 32; d <<= 1) {
            int u = __shfl_up_sync(0xffffffffu, wv, d);
            if (lane >= d) wv += u;
        }
        wtot[lane] = wv;
    }
    __syncthreads();
    int local_excl = (s - tsum) + (wid ? wtot[wid - 1] : 0);
    int block_total = wtot[31];

    if (t == 0)
        pub[b] = (1ULL << 32) | (unsigned)block_total;
    if (t < b) {
        ull pv;
        do { pv = pub[t]; } while ((pv >> 32) == 0);
        preds[t] = (int)(unsigned)pv;
    }
    __syncthreads();
    if (t == 0) {
        int r = 0;
        for (int j = 0; j < b; j++) r += preds[j];
        bp_sh = r;
    }
    __syncthreads();

    int off = bp_sh + local_excl;
    #pragma unroll
    for (int j = 0; j < 4; j++) {
        int idx = base + j;
        if (idx < n_nodes) {
            g_start[idx] = off;
            g_cnt[idx]   = off;
            if (idx == n_nodes - 1) g_start[n_nodes] = off + v[j];
            off += v[j];
        }
    }
}

extern "C" __global__ void rgcn_fill(const int*   __restrict__ esrc,
                                     const int*   __restrict__ edst,
                                     const float* __restrict__ ew,
                                     int n_edges)
{
    int e = blockIdx.x * blockDim.x + threadIdx.x;
    if (e >= n_edges) return;
    int d = edst[e];
    int pos = atomicAdd(&g_cnt[d], 1);
    __half hw = __float2half_rn(ew[e]);
    g_elist[pos] = (uint32_t)esrc[e] | ((uint32_t)*(unsigned short*)&hw << 16);
}

// ---------------------------------------------------------------------------
// Aggregate: one warp per dst node; each lane owns 2 outputs. No atomics.
// ---------------------------------------------------------------------------
__device__ __forceinline__ float2 yfrag(uint32_t src, int lane)
{
    unsigned q = *((const unsigned*)g_y + ((size_t)src << 5) + lane);
    __half2 h; *(unsigned*)&h = q;
    return __half22float2(h);
}

extern "C" __global__ void __launch_bounds__(256, 8)
rgcn_aggregate(float* __restrict__ out, int n_nodes)
{
    int gid = blockIdx.x * blockDim.x + threadIdx.x;
    int n = gid >> 5;
    if (n >= n_nodes) return;
    int lane = gid & 31;
    int e  = g_start[n];
    int e1 = g_start[n + 1];
    float2 acc = make_float2(0.f, 0.f);

    for (; e + 8 <= e1; e += 8) {
        uint32_t p[8];
        #pragma unroll
        for (int j = 0; j < 8; j++) p[j] = g_elist[e + j];
        float2 f[8];
        #pragma unroll
        for (int j = 0; j < 8; j++) f[j] = yfrag(p[j] & 0xFFFFu, lane);
        #pragma unroll
        for (int j = 0; j < 8; j++) {
            unsigned short wb = (unsigned short)(p[j] >> 16);
            float w = __half2float(*(__half*)&wb);
            acc.x += w * f[j].x;
            acc.y += w * f[j].y;
        }
    }
    if (e + 4 <= e1) {
        uint32_t p[4];
        #pragma unroll
        for (int j = 0; j < 4; j++) p[j] = g_elist[e + j];
        float2 f[4];
        #pragma unroll
        for (int j = 0; j < 4; j++) f[j] = yfrag(p[j] & 0xFFFFu, lane);
        #pragma unroll
        for (int j = 0; j < 4; j++) {
            unsigned short wb = (unsigned short)(p[j] >> 16);
            float w = __half2float(*(__half*)&wb);
            acc.x += w * f[j].x;
            acc.y += w * f[j].y;
        }
        e += 4;
    }
    for (; e < e1; e++) {
        uint32_t p = g_elist[e];
        float2 f = yfrag(p & 0xFFFFu, lane);
        unsigned short wb = (unsigned short)(p >> 16);
        float w = __half2float(*(__half*)&wb);
        acc.x += w * f.x;
        acc.y += w * f.y;
    }
    *(float2*)(out + (size_t)n * D_OUT + lane * 2) = acc;
}

// ---------------------------------------------------------------------------
extern "C" void kernel_launch(void* const* d_in, const int* in_sizes, int n_in,
                              void* d_out, int out_size)
{
    const float* x    = (const float*)d_in[0];
    const int*   esrc = (const int*)  d_in[1];
    const int*   edst = (const int*)  d_in[2];
    const float* ew   = (const float*)d_in[3];
    const float* wb   = (const float*)d_in[4];
    const float* wrel = (const float*)d_in[5];
    float* out = (float*)d_out;

    const int n_nodes = in_sizes[0] / (D_FEAT * N_REL);
    const int n_edges = in_sizes[1];
    const int n_tiles = (n_nodes + MTILE - 1) / MTILE;
    const int scan_blocks = (n_nodes + SCAN_PER - 1) / SCAN_PER;
    const int tgrid = n_tiles < TGRID ? n_tiles : TGRID;

    const int mma_smem = KTOT * LDP * 2 + 2 * MTILE * LDP * 2;   // 110592
    cudaFuncSetAttribute(rgcn_transform_mma,
                         cudaFuncAttributeMaxDynamicSharedMemorySize, mma_smem);

    // fork stream + events (host-side; outside graph replay cost)
    cudaStream_t s1;
    cudaStreamCreateWithFlags(&s1, cudaStreamNonBlocking);
    cudaEvent_t evFork, evJoin;
    cudaEventCreateWithFlags(&evFork, cudaEventDisableTiming);
    cudaEventCreateWithFlags(&evJoin, cudaEventDisableTiming);

    // branch A (s1): weights + counter init + HMMA transform (dynamic tiles)
    cudaEventRecord(evFork, 0);
    cudaStreamWaitEvent(s1, evFork, 0);
    rgcn_wt_build<<<(KTOT * D_OUT + 255) / 256, 256, 0, s1>>>(wb, wrel, tgrid);
    rgcn_transform_mma<<<tgrid, TBLOCK, mma_smem, s1>>>(x, n_nodes, n_tiles);
    cudaEventRecord(evJoin, s1);

    // branch B (main): CSR build by dst. One memset covers counters + pub tail.
    void* cnt_ptr = nullptr;
    cudaGetSymbolAddress(&cnt_ptr, g_cnt);
    size_t zero_bytes = (size_t)(((n_nodes + 1) & ~1) + 32) * sizeof(int);
    cudaMemsetAsync(cnt_ptr, 0, zero_bytes, 0);

    rgcn_hist<<<(n_edges + 255) / 256, 256>>>(edst, n_edges);
    rgcn_scan_fused<<<scan_blocks, 1024>>>(n_nodes);
    rgcn_fill<<<(n_edges + 255) / 256, 256>>>(esrc, edst, ew, n_edges);

    // join, then gather-aggregate
    cudaStreamWaitEvent(0, evJoin, 0);
    int total_thr = n_nodes * 32;
    rgcn_aggregate<<<(total_thr + 255) / 256, 256>>>(out, n_nodes);
}